// round 16
// baseline (speedup 1.0000x reference)
#include <cuda_runtime.h>
#include <cuda_bf16.h>
#include <cuda_fp16.h>
#include <math.h>
#include <stdint.h>

#define BSZ   8
#define LSEQ  2048
#define HDIM  512
#define NST   64
#define ROWS  (BSZ*LSEQ)      // 16384
#define SEG   16
#define SEGT  (LSEQ/SEG)      // 128
#define NROW  (BSZ*SEG)       // 128 rows per h (b,seg)

typedef __half fp16;
typedef __half2 fp162;

// ---------------- scratch ----------------------------------------------------------
__device__ float g_wre[HDIM*NST];
__device__ float g_wim[HDIM*NST];
__device__ float g_wTre[HDIM*NST];
__device__ float g_wTim[HDIM*NST];
__device__ float g_ctre[HDIM*NST];
__device__ float g_ctim[HDIM*NST];

__device__ float g_Kk[HDIM*SEGT];                        // conv kernel per h
__device__ fp16  g_usplit[(size_t)HDIM*NROW*256];        // [h][row][uh(128)|ul(128)]
__device__ fp16  g_WF[(size_t)HDIM*128*256];             // [h][n2][F|F]
__device__ fp16  g_WY[(size_t)HDIM*SEGT*512];            // [h][l][Th|Th|Tl|Ecat]
__device__ float g_send2[(size_t)HDIM*NROW*128];         // [h][row][re(64)|im(64)]
__device__ fp16  g_car[(size_t)HDIM*NROW*128];           // [h][row][cre(64)|cim(64)]
__device__ fp16  g_yT[(size_t)HDIM*BSZ*LSEQ];            // [h][b*L + l]

__device__ fp16  g_yf [(size_t)ROWS*HDIM];   // S4 activation (fp16), (B,L,H)
__device__ fp16  g_zf [(size_t)ROWS*2*HDIM]; // GLU pre-activation (fp16)
__device__ float g_xln[(size_t)ROWS*HDIM];
__device__ fp16  g_xf [(size_t)ROWS*HDIM];
__device__ fp16  g_y1f[(size_t)ROWS*HDIM];
__device__ float g_y2 [(size_t)ROWS*HDIM];

__device__ fp16 g_woutf[2*HDIM*HDIM];
__device__ fp16 g_w1f[HDIM*HDIM];
__device__ fp16 g_w2f[HDIM*HDIM];

// =============================== helpers =========================================
__device__ __forceinline__ uint32_t smem_u32(const void* p) {
    uint32_t a;
    asm("{ .reg .u64 t; cvta.to.shared.u64 t, %1; cvt.u32.u64 %0, t; }" : "=r"(a) : "l"(p));
    return a;
}

__device__ __forceinline__ void ldmatrix_x4(uint32_t* r, uint32_t addr) {
    asm volatile("ldmatrix.sync.aligned.m8n8.x4.shared.b16 {%0,%1,%2,%3}, [%4];"
        : "=r"(r[0]), "=r"(r[1]), "=r"(r[2]), "=r"(r[3]) : "r"(addr));
}

__device__ __forceinline__ void mma_f16(float* c, const uint32_t* a,
                                        uint32_t b0, uint32_t b1) {
    asm volatile("mma.sync.aligned.m16n8k16.row.col.f32.f16.f16.f32 "
        "{%0,%1,%2,%3}, {%4,%5,%6,%7}, {%8,%9}, {%0,%1,%2,%3};"
        : "+f"(c[0]), "+f"(c[1]), "+f"(c[2]), "+f"(c[3])
        : "r"(a[0]), "r"(a[1]), "r"(a[2]), "r"(a[3]), "r"(b0), "r"(b1));
}

#define CP_ASYNC16(saddr, gaddr) \
    asm volatile("cp.async.cg.shared.global [%0], [%1], 16;" \
                 :: "r"(saddr), "l"(gaddr) : "memory")
#define CP_COMMIT() asm volatile("cp.async.commit_group;" ::: "memory")
#define CP_WAIT(n)  asm volatile("cp.async.wait_group %0;" :: "n"(n) : "memory")

__device__ __forceinline__ float gelu_f(float v) {
    float c = 0.7978845608028654f * (v + 0.044715f * v * v * v);
    return v / (1.0f + __expf(-2.0f * c));
}

// ---------------- precompute w, w^SEGT, Ct ------------------------------------------
__global__ void precompute_kernel(const float* __restrict__ log_dt,
                                  const float* __restrict__ Are,
                                  const float* __restrict__ Aim,
                                  const float* __restrict__ Cre,
                                  const float* __restrict__ Cim) {
    int h = blockIdx.x, n = threadIdx.x;
    int idx = h * NST + n;
    float dt = expf(log_dt[h]);
    float ar = Are[idx] * dt;
    float ai = Aim[idx] * dt;
    float e  = expf(ar);
    float sb, cb;
    sincosf(ai, &sb, &cb);
    float wre = e * cb, wim = e * sb;
    float eT = expf(ar * (float)SEGT);
    float sT, cT;
    sincosf(ai * (float)SEGT, &sT, &cT);
    g_wTre[idx] = eT * cT;
    g_wTim[idx] = eT * sT;

    float Ere = wre - 1.0f, Eim = wim;
    float Ar = Are[idx], Ai = Aim[idx];
    float inv = 1.0f / (Ar * Ar + Ai * Ai);
    float rre = (Ere * Ar + Eim * Ai) * inv;
    float rim = (Eim * Ar - Ere * Ai) * inv;
    float cr = Cre[idx], ci = Cim[idx];
    g_ctre[idx] = cr * rre - ci * rim;
    g_ctim[idx] = cr * rim + ci * rre;
    g_wre[idx]  = wre;
    g_wim[idx]  = wim;
}

// ---------------- x -> Usplit: transpose + fp16 hi/lo split -------------------------
__global__ __launch_bounds__(256) void transpose_split_kernel(const float* __restrict__ x) {
    __shared__ float tile[32][33];
    int b  = blockIdx.z;
    int l0 = blockIdx.x * 32, h0 = blockIdx.y * 32;
    int tx = threadIdx.x & 31, ty = threadIdx.x >> 5;
    const float* xp = x + (size_t)b * LSEQ * HDIM;
#pragma unroll
    for (int i = 0; i < 32; i += 8)
        tile[ty + i][tx] = xp[(size_t)(l0 + ty + i) * HDIM + h0 + tx];
    __syncthreads();
#pragma unroll
    for (int i = 0; i < 32; i += 8) {
        int h = h0 + ty + i;
        int l = l0 + tx;
        int seg = l >> 7, m = l & 127;
        float v = tile[tx][ty + i];
        fp16 uh = __float2half_rn(v);
        fp16 ul = __float2half_rn(v - __half2float(uh));
        size_t base = ((size_t)h * NROW + b * SEG + seg) * 256 + m;
        g_usplit[base] = uh;
        g_usplit[base + 128] = ul;
    }
}

// ---------------- build Kk + E columns (coalesced, single sync) ---------------------
__global__ __launch_bounds__(128) void build_kk_e_kernel() {
    __shared__ float pre[SEGT][65];
    int h = blockIdx.x, tid = threadIdx.x;
    if (tid < 64) {
        int n = tid;
        float wr = g_wre[h * NST + n], wi = g_wim[h * NST + n];
        float pr = g_ctre[h * NST + n], pi = g_ctim[h * NST + n];  // Ct w^0
        for (int d = 0; d <= SEGT; ++d) {
            if (d < SEGT) pre[d][n] = pr;
            if (d >= 1) {
                size_t eb = ((size_t)h * SEGT + (d - 1)) * 512;
                g_WY[eb + 384 + n] = __float2half_rn(2.0f * pr);
                g_WY[eb + 448 + n] = __float2half_rn(-2.0f * pi);
            }
            float npr = pr * wr - pi * wi;
            float npi = pr * wi + pi * wr;
            pr = npr; pi = npi;
        }
    }
    __syncthreads();
    float s = 0.0f;
#pragma unroll 8
    for (int n = 0; n < 64; ++n) s += pre[tid][n];
    g_Kk[h * SEGT + tid] = 2.0f * s;
}

// ---------------- build Toeplitz hi/lo columns (coalesced m-sweep) ------------------
__global__ __launch_bounds__(256) void build_t_kernel(const float* __restrict__ Dskip) {
    __shared__ float kk[SEGT];
    __shared__ float dv;
    int h = blockIdx.x, tid = threadIdx.x;
    if (tid < SEGT) kk[tid] = g_Kk[h * SEGT + tid];
    if (tid == 0) dv = Dskip[h];
    __syncthreads();
#pragma unroll 4
    for (int r = 0; r < SEGT; r += 2) {
        int l = r + (tid >> 7);
        int m = tid & 127;
        float t = (m <= l) ? kk[l - m] : 0.0f;
        if (m == l) t += dv;
        fp16 th = __float2half_rn(t);
        fp16 tl = __float2half_rn(t - __half2float(th));
        size_t base = ((size_t)h * SEGT + l) * 512;
        g_WY[base + m] = th;
        g_WY[base + 128 + m] = th;
        g_WY[base + 256 + m] = tl;
    }
}

// ---------------- build WF (powers in smem, coalesced row writes) -------------------
__global__ __launch_bounds__(256) void build_wf_kernel() {
    __shared__ fp16 pwr[SEGT][66];
    __shared__ fp16 pwi[SEGT][66];
    int h = blockIdx.x, tid = threadIdx.x;
    if (tid < 64) {
        int n = tid;
        float wr = g_wre[h * NST + n], wi = g_wim[h * NST + n];
        float pr = 1.0f, pi = 0.0f;
        for (int s = 0; s < SEGT; ++s) {
            int m = SEGT - 1 - s;
            pwr[m][n] = __float2half_rn(pr);
            pwi[m][n] = __float2half_rn(pi);
            float npr = pr * wr - pi * wi;
            float npi = pr * wi + pi * wr;
            pr = npr; pi = npi;
        }
    }
    __syncthreads();
    int m = tid & 127;
#pragma unroll 4
    for (int row = 0; row < 128; ++row) {
        fp16 v = (row < 64) ? pwr[m][row] : pwi[m][row - 64];
        g_WF[((size_t)h * 128 + row) * 256 + tid] = v;
    }
}

// ====================== scan GEMM machinery (one CTA per h, KC=32) =================
#define LDSB   80
#define TILEB  (128 * LDSB)
#define STAGEB (2 * TILEB)
#define NSTAGE 3
#define SCAN_SMEM (NSTAGE * STAGEB) // 61440 bytes

// ---------------- send GEMM: send2 = (Uh+Ul) @ F^T  (K=256, fp32 out) ---------------
__global__ void __launch_bounds__(256, 2) send_gemm() {
    extern __shared__ char smem[];
    uint32_t sbase = smem_u32(smem);
    int tid = threadIdx.x, wid = tid >> 5, lane = tid & 31;
    int h = blockIdx.x;
    int wm = wid >> 1, wn = wid & 1;

    float acc[2][8][4];
#pragma unroll
    for (int i = 0; i < 2; i++)
#pragma unroll
        for (int j = 0; j < 8; j++)
#pragma unroll
            for (int q = 0; q < 4; q++) acc[i][j][q] = 0.0f;

    int lr = tid >> 1;
    int lc = (tid & 1) * 16;
    const fp16* ap = g_usplit + ((size_t)h * NROW + lr) * 256 + lc;
    const fp16* bp = g_WF + ((size_t)h * 128 + lr) * 256 + lc;
    uint32_t soff = (uint32_t)(lr * LDSB + lc * 2);

    const int nch = 8;
    auto issue = [&](int c, int s) {
        uint32_t st = sbase + (uint32_t)s * STAGEB;
        int go = c * 32;
        CP_ASYNC16(st + soff,      ap + go);
        CP_ASYNC16(st + soff + 16, ap + go + 8);
        CP_ASYNC16(st + TILEB + soff,      bp + go);
        CP_ASYNC16(st + TILEB + soff + 16, bp + go + 8);
    };
    issue(0, 0); CP_COMMIT();
    issue(1, 1); CP_COMMIT();

    int r_lm = (lane & 7) + ((lane >> 3) & 1) * 8;
    int k_lm = ((lane >> 4) & 1) * 8;

    for (int c = 0; c < nch; ++c) {
        CP_WAIT(1);
        __syncthreads();
        if (c + 2 < nch) { issue(c + 2, (c + 2) % NSTAGE); CP_COMMIT(); }
        uint32_t st = sbase + (uint32_t)(c % NSTAGE) * STAGEB;
#pragma unroll
        for (int ks = 0; ks < 2; ++ks) {
            int kcol = ks * 16 + k_lm;
            uint32_t af[2][4];
#pragma unroll
            for (int mi = 0; mi < 2; ++mi)
                ldmatrix_x4(af[mi], st + (uint32_t)((wm * 32 + mi * 16 + r_lm) * LDSB + kcol * 2));
#pragma unroll
            for (int nj = 0; nj < 4; ++nj) {
                uint32_t bf[4];
                ldmatrix_x4(bf, st + TILEB + (uint32_t)((wn * 64 + nj * 16 + r_lm) * LDSB + kcol * 2));
#pragma unroll
                for (int mi = 0; mi < 2; ++mi)
#pragma unroll
                    for (int q = 0; q < 2; ++q)
                        mma_f16(acc[mi][nj * 2 + q], af[mi], bf[q], bf[2 + q]);
            }
        }
    }

    int tg = lane >> 2, tq = lane & 3;
#pragma unroll
    for (int mi = 0; mi < 2; ++mi) {
        int r = wm * 32 + mi * 16 + tg;
#pragma unroll
        for (int ni = 0; ni < 8; ++ni) {
            int cix = wn * 64 + ni * 8 + tq * 2;
            *(float2*)(g_send2 + ((size_t)h * NROW + r) * 128 + cix) =
                make_float2(acc[mi][ni][0], acc[mi][ni][1]);
            *(float2*)(g_send2 + ((size_t)h * NROW + r + 8) * 128 + cix) =
                make_float2(acc[mi][ni][2], acc[mi][ni][3]);
        }
    }
}

// ---------------- combine ------------------------------------------------------------
__global__ __launch_bounds__(256) void combine_kernel() {
    int idx = blockIdx.x * blockDim.x + threadIdx.x;
    int n = idx & (NST - 1);
    int b = (idx >> 6) & (BSZ - 1);
    int h = idx >> 9;
    float wTre = g_wTre[h * NST + n];
    float wTim = g_wTim[h * NST + n];
    float cr = 0.0f, ci = 0.0f;
#pragma unroll
    for (int seg = 0; seg < SEG; ++seg) {
        size_t cb = ((size_t)h * NROW + b * SEG + seg) * 128;
        g_car[cb + n]      = __float2half_rn(cr);
        g_car[cb + 64 + n] = __float2half_rn(ci);
        if (seg < SEG - 1) {
            float sr = g_send2[cb + n];
            float si = g_send2[cb + 64 + n];
            float nr = fmaf(wTre, cr, fmaf(-wTim, ci, sr));
            float ni = fmaf(wTim, cr, fmaf(wTre, ci, si));
            cr = nr; ci = ni;
        }
    }
}

// ---------------- scan GEMM: yT = gelu([Uh|Ul|Uh|CAR] @ [Th|Th|Tl|E]^T) -------------
__global__ void __launch_bounds__(256, 2) scan_gemm() {
    extern __shared__ char smem[];
    uint32_t sbase = smem_u32(smem);
    int tid = threadIdx.x, wid = tid >> 5, lane = tid & 31;
    int h = blockIdx.x;
    int wm = wid >> 1, wn = wid & 1;

    float acc[2][8][4];
#pragma unroll
    for (int i = 0; i < 2; i++)
#pragma unroll
        for (int j = 0; j < 8; j++)
#pragma unroll
            for (int q = 0; q < 4; q++) acc[i][j][q] = 0.0f;

    int lr = tid >> 1;
    int lc = (tid & 1) * 16;
    const fp16* up = g_usplit + ((size_t)h * NROW + lr) * 256 + lc;
    const fp16* cp = g_car + ((size_t)h * NROW + lr) * 128 + lc;
    const fp16* wp = g_WY + ((size_t)h * SEGT + lr) * 512 + lc;
    uint32_t soff = (uint32_t)(lr * LDSB + lc * 2);

    const int nch = 16;
    auto issue = [&](int c, int s) {
        uint32_t st = sbase + (uint32_t)s * STAGEB;
        const fp16* ab; int ga;
        if (c < 8)       { ab = up; ga = c * 32; }
        else if (c < 12) { ab = up; ga = (c - 8) * 32; }
        else             { ab = cp; ga = (c - 12) * 32; }
        CP_ASYNC16(st + soff,      ab + ga);
        CP_ASYNC16(st + soff + 16, ab + ga + 8);
        int gw = c * 32;
        CP_ASYNC16(st + TILEB + soff,      wp + gw);
        CP_ASYNC16(st + TILEB + soff + 16, wp + gw + 8);
    };
    issue(0, 0); CP_COMMIT();
    issue(1, 1); CP_COMMIT();

    int r_lm = (lane & 7) + ((lane >> 3) & 1) * 8;
    int k_lm = ((lane >> 4) & 1) * 8;

    for (int c = 0; c < nch; ++c) {
        CP_WAIT(1);
        __syncthreads();
        if (c + 2 < nch) { issue(c + 2, (c + 2) % NSTAGE); CP_COMMIT(); }
        uint32_t st = sbase + (uint32_t)(c % NSTAGE) * STAGEB;
#pragma unroll
        for (int ks = 0; ks < 2; ++ks) {
            int kcol = ks * 16 + k_lm;
            uint32_t af[2][4];
#pragma unroll
            for (int mi = 0; mi < 2; ++mi)
                ldmatrix_x4(af[mi], st + (uint32_t)((wm * 32 + mi * 16 + r_lm) * LDSB + kcol * 2));
#pragma unroll
            for (int nj = 0; nj < 4; ++nj) {
                uint32_t bf[4];
                ldmatrix_x4(bf, st + TILEB + (uint32_t)((wn * 64 + nj * 16 + r_lm) * LDSB + kcol * 2));
#pragma unroll
                for (int mi = 0; mi < 2; ++mi)
#pragma unroll
                    for (int q = 0; q < 2; ++q)
                        mma_f16(acc[mi][nj * 2 + q], af[mi], bf[q], bf[2 + q]);
            }
        }
    }

    int tg = lane >> 2, tq = lane & 3;
#pragma unroll
    for (int mi = 0; mi < 2; ++mi) {
        int r = wm * 32 + mi * 16 + tg;
#pragma unroll
        for (int ni = 0; ni < 8; ++ni) {
            int cix = wn * 64 + ni * 8 + tq * 2;
            float v0 = gelu_f(acc[mi][ni][0]), v1 = gelu_f(acc[mi][ni][1]);
            float v2 = gelu_f(acc[mi][ni][2]), v3 = gelu_f(acc[mi][ni][3]);
            *(fp162*)(g_yT + ((size_t)h * NROW + r) * SEGT + cix) = __floats2half2_rn(v0, v1);
            *(fp162*)(g_yT + ((size_t)h * NROW + r + 8) * SEGT + cix) = __floats2half2_rn(v2, v3);
        }
    }
}

// ---------------- yT (H, B*L) -> yf (B*L, H) fp16 transpose --------------------------
__global__ __launch_bounds__(256) void yt_transpose_kernel() {
    __shared__ fp16 tile[32][34];
    int bl0 = blockIdx.x * 32, h0 = blockIdx.y * 32;
    int tx = threadIdx.x & 31, ty = threadIdx.x >> 5;
#pragma unroll
    for (int i = 0; i < 32; i += 8)
        tile[ty + i][tx] = g_yT[(size_t)(h0 + ty + i) * (BSZ * LSEQ) + bl0 + tx];
    __syncthreads();
#pragma unroll
    for (int i = 0; i < 32; i += 8)
        g_yf[(size_t)(bl0 + ty + i) * HDIM + h0 + tx] = tile[tx][ty + i];
}

// ---------------- weight convert -----------------------------------------------------
__global__ void convert_w_kernel(const float* __restrict__ wout,
                                 const float* __restrict__ w1,
                                 const float* __restrict__ w2) {
    int i = blockIdx.x * blockDim.x + threadIdx.x;
    const int n1 = 2 * HDIM * HDIM;
    const int n2 = HDIM * HDIM;
    if (i < n1) {
        g_woutf[i] = __float2half_rn(wout[i]);
    } else if (i < n1 + n2) {
        g_w1f[i - n1] = __float2half_rn(w1[i - n1]);
    } else {
        g_w2f[i - n1 - n2] = __float2half_rn(w2[i - n1 - n2]);
    }
}

// ============ main GEMM: C = A_f16 @ B_f16^T + bias, KC=64 chunks ==================
#define MLDSB   144                   // 64 fp16 + 8 pad per row
#define MTILEB  (128 * MLDSB)         // 18432
#define MSTAGEB (2 * MTILEB)          // 36864
#define MNSTAGE 3
#define MAIN_SMEM (MNSTAGE * MSTAGEB) // 110592 -> 2 CTAs/SM

// mode 0: fp32 out ; 1: relu + fp16 out ; 2: fp16 out (no relu)
__global__ void __launch_bounds__(256, 2)
gemm_mma(const fp16* __restrict__ A, const fp16* __restrict__ B,
         const float* __restrict__ bias,
         float* __restrict__ C, fp16* __restrict__ Cf,
         int K, int N, int mode) {
    extern __shared__ char smem[];
    uint32_t sbase = smem_u32(smem);
    int tid = threadIdx.x, wid = tid >> 5, lane = tid & 31;
    int row0 = blockIdx.y * 128, col0 = blockIdx.x * 128;
    int wm = wid >> 1, wn = wid & 1;

    float acc[2][8][4];
#pragma unroll
    for (int i = 0; i < 2; i++)
#pragma unroll
        for (int j = 0; j < 8; j++)
#pragma unroll
            for (int q = 0; q < 4; q++) acc[i][j][q] = 0.0f;

    int lr = tid >> 1;
    int lc = (tid & 1) * 32;          // 32 fp16 = 64 B per thread per tile
    const fp16* ap = A + (size_t)(row0 + lr) * K + lc;
    const fp16* bp = B + (size_t)(col0 + lr) * K + lc;
    uint32_t soff = (uint32_t)(lr * MLDSB + lc * 2);

    int nch = K / 64;

    auto issue = [&](int c, int s) {
        uint32_t st = sbase + (uint32_t)s * MSTAGEB;
        int go = c * 64;
        CP_ASYNC16(st + soff,      ap + go);
        CP_ASYNC16(st + soff + 16, ap + go + 8);
        CP_ASYNC16(st + soff + 32, ap + go + 16);
        CP_ASYNC16(st + soff + 48, ap + go + 24);
        uint32_t bb = st + MTILEB + soff;
        CP_ASYNC16(bb,      bp + go);
        CP_ASYNC16(bb + 16, bp + go + 8);
        CP_ASYNC16(bb + 32, bp + go + 16);
        CP_ASYNC16(bb + 48, bp + go + 24);
    };

    issue(0, 0); CP_COMMIT();
    if (nch > 1) { issue(1, 1); CP_COMMIT(); }

    int r_lm = (lane & 7) + ((lane >> 3) & 1) * 8;
    int k_lm = ((lane >> 4) & 1) * 8;

    for (int c = 0; c < nch; ++c) {
        CP_WAIT(1);
        __syncthreads();
        if (c + 2 < nch) { issue(c + 2, (c + 2) % MNSTAGE); CP_COMMIT(); }

        uint32_t st = sbase + (uint32_t)(c % MNSTAGE) * MSTAGEB;
#pragma unroll
        for (int ks = 0; ks < 4; ++ks) {
            int kcol = ks * 16 + k_lm;
            uint32_t af[2][4];
#pragma unroll
            for (int mi = 0; mi < 2; ++mi)
                ldmatrix_x4(af[mi], st + (uint32_t)((wm * 32 + mi * 16 + r_lm) * MLDSB + kcol * 2));
#pragma unroll
            for (int nj = 0; nj < 4; ++nj) {
                uint32_t bf[4];
                ldmatrix_x4(bf, st + MTILEB + (uint32_t)((wn * 64 + nj * 16 + r_lm) * MLDSB + kcol * 2));
#pragma unroll
                for (int mi = 0; mi < 2; ++mi)
#pragma unroll
                    for (int q = 0; q < 2; ++q)
                        mma_f16(acc[mi][nj * 2 + q], af[mi], bf[q], bf[2 + q]);
            }
        }
    }

    int tg = lane >> 2, tq = lane & 3;
#pragma unroll
    for (int mi = 0; mi < 2; ++mi) {
        int r = row0 + wm * 32 + mi * 16 + tg;
#pragma unroll
        for (int ni = 0; ni < 8; ++ni) {
            int cix = col0 + wn * 64 + ni * 8 + tq * 2;
            float b0 = bias[cix], b1 = bias[cix + 1];
            float v0 = acc[mi][ni][0] + b0, v1 = acc[mi][ni][1] + b1;
            float v2 = acc[mi][ni][2] + b0, v3 = acc[mi][ni][3] + b1;
            if (mode == 0) {
                *(float2*)(C + (size_t)r * N + cix) = make_float2(v0, v1);
                *(float2*)(C + (size_t)(r + 8) * N + cix) = make_float2(v2, v3);
            } else {
                if (mode == 1) {
                    v0 = fmaxf(v0, 0.0f); v1 = fmaxf(v1, 0.0f);
                    v2 = fmaxf(v2, 0.0f); v3 = fmaxf(v3, 0.0f);
                }
                *(fp162*)(Cf + (size_t)r * N + cix) = __floats2half2_rn(v0, v1);
                *(fp162*)(Cf + (size_t)(r + 8) * N + cix) = __floats2half2_rn(v2, v3);
            }
        }
    }
}

// ---------------- block reduce helper ---------------------------------------------
__device__ __forceinline__ float2 block_reduce_2(float a, float b) {
    unsigned m = 0xffffffffu;
#pragma unroll
    for (int o = 16; o > 0; o >>= 1) {
        a += __shfl_down_sync(m, a, o);
        b += __shfl_down_sync(m, b, o);
    }
    __shared__ float sa[4], sb[4];
    int w = threadIdx.x >> 5, lane = threadIdx.x & 31;
    if (lane == 0) { sa[w] = a; sb[w] = b; }
    __syncthreads();
    if (threadIdx.x == 0) {
        float ta = sa[0] + sa[1] + sa[2] + sa[3];
        float tb = sb[0] + sb[1] + sb[2] + sb[3];
        sa[0] = ta; sb[0] = tb;
    }
    __syncthreads();
    return make_float2(sa[0], sb[0]);
}

// ---------------- GLU + residual + LN1 (fp16 z in) ---------------------------------
__global__ __launch_bounds__(128) void glu_ln_kernel(const fp16* __restrict__ z,
                                                     const float* __restrict__ x,
                                                     const float* __restrict__ g1,
                                                     const float* __restrict__ b1,
                                                     float* __restrict__ xln,
                                                     fp16* __restrict__ xf) {
    int row = blockIdx.x, tid = threadIdx.x;
    const fp162* zr = (const fp162*)(z + (size_t)row * (2 * HDIM));
    const float4* xr = (const float4*)(x + (size_t)row * HDIM);
    fp162 a01 = zr[tid * 2], a23 = zr[tid * 2 + 1];
    fp162 g01 = zr[256 + tid * 2], g23 = zr[256 + tid * 2 + 1];
    float4 xv = xr[tid];
    float2 a0 = __half22float2(a01), a2 = __half22float2(a23);
    float2 gg0 = __half22float2(g01), gg2 = __half22float2(g23);
    float4 v;
    v.x = xv.x + a0.x / (1.0f + __expf(-gg0.x));
    v.y = xv.y + a0.y / (1.0f + __expf(-gg0.y));
    v.z = xv.z + a2.x / (1.0f + __expf(-gg2.x));
    v.w = xv.w + a2.y / (1.0f + __expf(-gg2.y));
    float s  = v.x + v.y + v.z + v.w;
    float s2 = v.x*v.x + v.y*v.y + v.z*v.z + v.w*v.w;
    float2 tot = block_reduce_2(s, s2);
    float mu = tot.x * (1.0f / HDIM);
    float var = tot.y * (1.0f / HDIM) - mu * mu;
    float rstd = rsqrtf(var + 1e-5f);
    float4 gv = ((const float4*)g1)[tid];
    float4 bv = ((const float4*)b1)[tid];
    float4 o;
    o.x = (v.x - mu) * rstd * gv.x + bv.x;
    o.y = (v.y - mu) * rstd * gv.y + bv.y;
    o.z = (v.z - mu) * rstd * gv.z + bv.z;
    o.w = (v.w - mu) * rstd * gv.w + bv.w;
    ((float4*)(xln + (size_t)row * HDIM))[tid] = o;
    fp162* xf2 = (fp162*)(xf + (size_t)row * HDIM);
    xf2[tid*2]   = __floats2half2_rn(o.x, o.y);
    xf2[tid*2+1] = __floats2half2_rn(o.z, o.w);
}

// ---------------- residual + LN2 ----------------------------------------------------
__global__ __launch_bounds__(128) void final_ln_kernel(const float* __restrict__ xln,
                                                       const float* __restrict__ y2,
                                                       const float* __restrict__ g2,
                                                       const float* __restrict__ b2,
                                                       float* __restrict__ out) {
    int row = blockIdx.x, tid = threadIdx.x;
    float4 a = ((const float4*)(xln + (size_t)row * HDIM))[tid];
    float4 b = ((const float4*)(y2  + (size_t)row * HDIM))[tid];
    float4 v;
    v.x = a.x + b.x; v.y = a.y + b.y; v.z = a.z + b.z; v.w = a.w + b.w;
    float s  = v.x + v.y + v.z + v.w;
    float s2 = v.x*v.x + v.y*v.y + v.z*v.z + v.w*v.w;
    float2 tot = block_reduce_2(s, s2);
    float mu = tot.x * (1.0f / HDIM);
    float var = tot.y * (1.0f / HDIM) - mu * mu;
    float rstd = rsqrtf(var + 1e-5f);
    float4 gv = ((const float4*)g2)[tid];
    float4 bv = ((const float4*)b2)[tid];
    float4 o;
    o.x = (v.x - mu) * rstd * gv.x + bv.x;
    o.y = (v.y - mu) * rstd * gv.y + bv.y;
    o.z = (v.z - mu) * rstd * gv.z + bv.z;
    o.w = (v.w - mu) * rstd * gv.w + bv.w;
    ((float4*)(out + (size_t)row * HDIM))[tid] = o;
}

// ---------------- launch ------------------------------------------------------------
extern "C" void kernel_launch(void* const* d_in, const int* in_sizes, int n_in,
                              void* d_out, int out_size) {
    const float* x      = (const float*)d_in[0];
    const float* log_dt = (const float*)d_in[1];
    const float* A_re   = (const float*)d_in[2];
    const float* A_im   = (const float*)d_in[3];
    const float* C_re   = (const float*)d_in[4];
    const float* C_im   = (const float*)d_in[5];
    const float* D_skip = (const float*)d_in[6];
    const float* W_out  = (const float*)d_in[7];
    const float* b_out  = (const float*)d_in[8];
    const float* g1     = (const float*)d_in[9];
    const float* beta1  = (const float*)d_in[10];
    const float* g2     = (const float*)d_in[11];
    const float* beta2  = (const float*)d_in[12];
    const float* W1     = (const float*)d_in[13];
    const float* bc1    = (const float*)d_in[14];
    const float* W2     = (const float*)d_in[15];
    const float* bc2    = (const float*)d_in[16];
    float* out = (float*)d_out;

    fp16 *yf, *zf, *xf, *y1f, *woutf, *w1f, *w2f;
    float *xln, *y2;
    cudaGetSymbolAddress((void**)&yf,  g_yf);
    cudaGetSymbolAddress((void**)&zf,  g_zf);
    cudaGetSymbolAddress((void**)&xln, g_xln);
    cudaGetSymbolAddress((void**)&xf,  g_xf);
    cudaGetSymbolAddress((void**)&y1f, g_y1f);
    cudaGetSymbolAddress((void**)&y2,  g_y2);
    cudaGetSymbolAddress((void**)&woutf, g_woutf);
    cudaGetSymbolAddress((void**)&w1f, g_w1f);
    cudaGetSymbolAddress((void**)&w2f, g_w2f);

    cudaFuncSetAttribute(gemm_mma,  cudaFuncAttributeMaxDynamicSharedMemorySize, MAIN_SMEM);
    cudaFuncSetAttribute(send_gemm, cudaFuncAttributeMaxDynamicSharedMemorySize, SCAN_SMEM);
    cudaFuncSetAttribute(scan_gemm, cudaFuncAttributeMaxDynamicSharedMemorySize, SCAN_SMEM);

    // 1) discretize + operator builds (coalesced)
    precompute_kernel<<<HDIM, NST>>>(log_dt, A_re, A_im, C_re, C_im);
    transpose_split_kernel<<<dim3(LSEQ / 32, HDIM / 32, BSZ), 256>>>(x);
    build_kk_e_kernel<<<HDIM, 128>>>();
    build_t_kernel<<<HDIM, 256>>>(D_skip);
    build_wf_kernel<<<HDIM, 256>>>();
    convert_w_kernel<<<(4 * HDIM * HDIM + 255) / 256, 256>>>(W_out, W1, W2);

    // 2) scan as GEMMs
    send_gemm<<<HDIM, 256, SCAN_SMEM>>>();
    combine_kernel<<<(HDIM * BSZ * NST) / 256, 256>>>();
    scan_gemm<<<HDIM, 256, SCAN_SMEM>>>();
    yt_transpose_kernel<<<dim3((BSZ * LSEQ) / 32, HDIM / 32), 256>>>();

    // 3) GLU projection (fp16 z out) + rest of layer
    gemm_mma<<<dim3((2 * HDIM) / 128, ROWS / 128), 256, MAIN_SMEM>>>(
        yf, woutf, b_out, nullptr, zf, HDIM, 2 * HDIM, 2);

    glu_ln_kernel<<<ROWS, 128>>>(zf, x, g1, beta1, xln, xf);

    gemm_mma<<<dim3(HDIM / 128, ROWS / 128), 256, MAIN_SMEM>>>(
        xf, w1f, bc1, nullptr, y1f, HDIM, HDIM, 1);

    gemm_mma<<<dim3(HDIM / 128, ROWS / 128), 256, MAIN_SMEM>>>(
        y1f, w2f, bc2, y2, nullptr, HDIM, HDIM, 0);

    final_ln_kernel<<<ROWS, 128>>>(xln, y2, g2, beta2, out);
}

// round 17
// speedup vs baseline: 1.0505x; 1.0505x over previous
#include <cuda_runtime.h>
#include <cuda_bf16.h>
#include <cuda_fp16.h>
#include <math.h>
#include <stdint.h>

#define BSZ   8
#define LSEQ  2048
#define HDIM  512
#define NST   64
#define ROWS  (BSZ*LSEQ)      // 16384
#define SEG   16
#define SEGT  (LSEQ/SEG)      // 128
#define NROW  (BSZ*SEG)       // 128 rows per h (b,seg)

typedef __half fp16;
typedef __half2 fp162;

// ---------------- scratch ----------------------------------------------------------
__device__ float g_wre[HDIM*NST];
__device__ float g_wim[HDIM*NST];
__device__ float g_wTre[HDIM*NST];
__device__ float g_wTim[HDIM*NST];
__device__ float g_ctre[HDIM*NST];
__device__ float g_ctim[HDIM*NST];

__device__ float g_Kk[HDIM*SEGT];                        // conv kernel per h
__device__ fp16  g_usplit[(size_t)HDIM*NROW*256];        // [h][row][uh(128)|ul(128)]
__device__ fp16  g_WF[(size_t)HDIM*128*256];             // [h][n2][F|F]
__device__ fp16  g_WY[(size_t)HDIM*SEGT*512];            // [h][l][Th|Th|Tl|Ecat]
__device__ float g_send2[(size_t)HDIM*NROW*128];         // [h][row][re(64)|im(64)]
__device__ fp16  g_car[(size_t)HDIM*NROW*128];           // [h][row][cre(64)|cim(64)]
__device__ fp16  g_yT[(size_t)HDIM*BSZ*LSEQ];            // [h][b*L + l]

__device__ fp16  g_yf [(size_t)ROWS*HDIM];   // S4 activation (fp16), (B,L,H)
__device__ fp16  g_zf [(size_t)ROWS*2*HDIM]; // GLU pre-activation (fp16)
__device__ float g_xln[(size_t)ROWS*HDIM];
__device__ fp16  g_xf [(size_t)ROWS*HDIM];
__device__ fp16  g_y1f[(size_t)ROWS*HDIM];
__device__ float g_y2 [(size_t)ROWS*HDIM];

__device__ fp16 g_woutf[2*HDIM*HDIM];
__device__ fp16 g_w1f[HDIM*HDIM];
__device__ fp16 g_w2f[HDIM*HDIM];

// =============================== helpers =========================================
__device__ __forceinline__ uint32_t smem_u32(const void* p) {
    uint32_t a;
    asm("{ .reg .u64 t; cvta.to.shared.u64 t, %1; cvt.u32.u64 %0, t; }" : "=r"(a) : "l"(p));
    return a;
}

__device__ __forceinline__ void ldmatrix_x4(uint32_t* r, uint32_t addr) {
    asm volatile("ldmatrix.sync.aligned.m8n8.x4.shared.b16 {%0,%1,%2,%3}, [%4];"
        : "=r"(r[0]), "=r"(r[1]), "=r"(r[2]), "=r"(r[3]) : "r"(addr));
}

__device__ __forceinline__ void mma_f16(float* c, const uint32_t* a,
                                        uint32_t b0, uint32_t b1) {
    asm volatile("mma.sync.aligned.m16n8k16.row.col.f32.f16.f16.f32 "
        "{%0,%1,%2,%3}, {%4,%5,%6,%7}, {%8,%9}, {%0,%1,%2,%3};"
        : "+f"(c[0]), "+f"(c[1]), "+f"(c[2]), "+f"(c[3])
        : "r"(a[0]), "r"(a[1]), "r"(a[2]), "r"(a[3]), "r"(b0), "r"(b1));
}

#define CP_ASYNC16(saddr, gaddr) \
    asm volatile("cp.async.cg.shared.global [%0], [%1], 16;" \
                 :: "r"(saddr), "l"(gaddr) : "memory")
#define CP_COMMIT() asm volatile("cp.async.commit_group;" ::: "memory")
#define CP_WAIT(n)  asm volatile("cp.async.wait_group %0;" :: "n"(n) : "memory")

__device__ __forceinline__ float gelu_f(float v) {
    float c = 0.7978845608028654f * (v + 0.044715f * v * v * v);
    return v / (1.0f + __expf(-2.0f * c));
}

// ---------------- precompute w, w^SEGT, Ct ------------------------------------------
__global__ void precompute_kernel(const float* __restrict__ log_dt,
                                  const float* __restrict__ Are,
                                  const float* __restrict__ Aim,
                                  const float* __restrict__ Cre,
                                  const float* __restrict__ Cim) {
    int h = blockIdx.x, n = threadIdx.x;
    int idx = h * NST + n;
    float dt = expf(log_dt[h]);
    float ar = Are[idx] * dt;
    float ai = Aim[idx] * dt;
    float e  = expf(ar);
    float sb, cb;
    sincosf(ai, &sb, &cb);
    float wre = e * cb, wim = e * sb;
    float eT = expf(ar * (float)SEGT);
    float sT, cT;
    sincosf(ai * (float)SEGT, &sT, &cT);
    g_wTre[idx] = eT * cT;
    g_wTim[idx] = eT * sT;

    float Ere = wre - 1.0f, Eim = wim;
    float Ar = Are[idx], Ai = Aim[idx];
    float inv = 1.0f / (Ar * Ar + Ai * Ai);
    float rre = (Ere * Ar + Eim * Ai) * inv;
    float rim = (Eim * Ar - Ere * Ai) * inv;
    float cr = Cre[idx], ci = Cim[idx];
    g_ctre[idx] = cr * rre - ci * rim;
    g_ctim[idx] = cr * rim + ci * rre;
    g_wre[idx]  = wre;
    g_wim[idx]  = wim;
}

// ---------------- x -> Usplit: transpose + fp16 hi/lo split -------------------------
__global__ __launch_bounds__(256) void transpose_split_kernel(const float* __restrict__ x) {
    __shared__ float tile[32][33];
    int b  = blockIdx.z;
    int l0 = blockIdx.x * 32, h0 = blockIdx.y * 32;
    int tx = threadIdx.x & 31, ty = threadIdx.x >> 5;
    const float* xp = x + (size_t)b * LSEQ * HDIM;
#pragma unroll
    for (int i = 0; i < 32; i += 8)
        tile[ty + i][tx] = xp[(size_t)(l0 + ty + i) * HDIM + h0 + tx];
    __syncthreads();
#pragma unroll
    for (int i = 0; i < 32; i += 8) {
        int h = h0 + ty + i;
        int l = l0 + tx;
        int seg = l >> 7, m = l & 127;
        float v = tile[tx][ty + i];
        fp16 uh = __float2half_rn(v);
        fp16 ul = __float2half_rn(v - __half2float(uh));
        size_t base = ((size_t)h * NROW + b * SEG + seg) * 256 + m;
        g_usplit[base] = uh;
        g_usplit[base + 128] = ul;
    }
}

// ---------------- build Kk + E columns (coalesced, single sync) ---------------------
__global__ __launch_bounds__(128) void build_kk_e_kernel() {
    __shared__ float pre[SEGT][65];
    int h = blockIdx.x, tid = threadIdx.x;
    if (tid < 64) {
        int n = tid;
        float wr = g_wre[h * NST + n], wi = g_wim[h * NST + n];
        float pr = g_ctre[h * NST + n], pi = g_ctim[h * NST + n];  // Ct w^0
        for (int d = 0; d <= SEGT; ++d) {
            if (d < SEGT) pre[d][n] = pr;
            if (d >= 1) {
                size_t eb = ((size_t)h * SEGT + (d - 1)) * 512;
                g_WY[eb + 384 + n] = __float2half_rn(2.0f * pr);
                g_WY[eb + 448 + n] = __float2half_rn(-2.0f * pi);
            }
            float npr = pr * wr - pi * wi;
            float npi = pr * wi + pi * wr;
            pr = npr; pi = npi;
        }
    }
    __syncthreads();
    float s = 0.0f;
#pragma unroll 8
    for (int n = 0; n < 64; ++n) s += pre[tid][n];
    g_Kk[h * SEGT + tid] = 2.0f * s;
}

// ---------------- build Toeplitz hi/lo columns (coalesced m-sweep) ------------------
__global__ __launch_bounds__(256) void build_t_kernel(const float* __restrict__ Dskip) {
    __shared__ float kk[SEGT];
    __shared__ float dv;
    int h = blockIdx.x, tid = threadIdx.x;
    if (tid < SEGT) kk[tid] = g_Kk[h * SEGT + tid];
    if (tid == 0) dv = Dskip[h];
    __syncthreads();
#pragma unroll 4
    for (int r = 0; r < SEGT; r += 2) {
        int l = r + (tid >> 7);
        int m = tid & 127;
        float t = (m <= l) ? kk[l - m] : 0.0f;
        if (m == l) t += dv;
        fp16 th = __float2half_rn(t);
        fp16 tl = __float2half_rn(t - __half2float(th));
        size_t base = ((size_t)h * SEGT + l) * 512;
        g_WY[base + m] = th;
        g_WY[base + 128 + m] = th;
        g_WY[base + 256 + m] = tl;
    }
}

// ---------------- build WF (powers in smem, coalesced row writes) -------------------
__global__ __launch_bounds__(256) void build_wf_kernel() {
    __shared__ fp16 pwr[SEGT][66];
    __shared__ fp16 pwi[SEGT][66];
    int h = blockIdx.x, tid = threadIdx.x;
    if (tid < 64) {
        int n = tid;
        float wr = g_wre[h * NST + n], wi = g_wim[h * NST + n];
        float pr = 1.0f, pi = 0.0f;
        for (int s = 0; s < SEGT; ++s) {
            int m = SEGT - 1 - s;
            pwr[m][n] = __float2half_rn(pr);
            pwi[m][n] = __float2half_rn(pi);
            float npr = pr * wr - pi * wi;
            float npi = pr * wi + pi * wr;
            pr = npr; pi = npi;
        }
    }
    __syncthreads();
    int m = tid & 127;
#pragma unroll 4
    for (int row = 0; row < 128; ++row) {
        fp16 v = (row < 64) ? pwr[m][row] : pwi[m][row - 64];
        g_WF[((size_t)h * 128 + row) * 256 + tid] = v;
    }
}

// ====================== GEMM machinery (KC=32, LDSB=80, 3-stage) ===================
#define LDSB   80
#define TILEB  (128 * LDSB)
#define STAGEB (2 * TILEB)
#define NSTAGE 3
#define GEMM_SMEM (NSTAGE * STAGEB) // 61440 bytes -> 2 CTAs/SM

// ---------------- send GEMM: send2 = (Uh+Ul) @ F^T  (K=256, fp32 out) ---------------
__global__ void __launch_bounds__(256, 2) send_gemm() {
    extern __shared__ char smem[];
    uint32_t sbase = smem_u32(smem);
    int tid = threadIdx.x, wid = tid >> 5, lane = tid & 31;
    int h = blockIdx.x;
    int wm = wid >> 1, wn = wid & 1;

    float acc[2][8][4];
#pragma unroll
    for (int i = 0; i < 2; i++)
#pragma unroll
        for (int j = 0; j < 8; j++)
#pragma unroll
            for (int q = 0; q < 4; q++) acc[i][j][q] = 0.0f;

    int lr = tid >> 1;
    int lc = (tid & 1) * 16;
    const fp16* ap = g_usplit + ((size_t)h * NROW + lr) * 256 + lc;
    const fp16* bp = g_WF + ((size_t)h * 128 + lr) * 256 + lc;
    uint32_t soff = (uint32_t)(lr * LDSB + lc * 2);

    const int nch = 8;
    auto issue = [&](int c, int s) {
        uint32_t st = sbase + (uint32_t)s * STAGEB;
        int go = c * 32;
        CP_ASYNC16(st + soff,      ap + go);
        CP_ASYNC16(st + soff + 16, ap + go + 8);
        CP_ASYNC16(st + TILEB + soff,      bp + go);
        CP_ASYNC16(st + TILEB + soff + 16, bp + go + 8);
    };
    issue(0, 0); CP_COMMIT();
    issue(1, 1); CP_COMMIT();

    int r_lm = (lane & 7) + ((lane >> 3) & 1) * 8;
    int k_lm = ((lane >> 4) & 1) * 8;

    for (int c = 0; c < nch; ++c) {
        CP_WAIT(1);
        __syncthreads();
        if (c + 2 < nch) { issue(c + 2, (c + 2) % NSTAGE); CP_COMMIT(); }
        uint32_t st = sbase + (uint32_t)(c % NSTAGE) * STAGEB;
#pragma unroll
        for (int ks = 0; ks < 2; ++ks) {
            int kcol = ks * 16 + k_lm;
            uint32_t af[2][4];
#pragma unroll
            for (int mi = 0; mi < 2; ++mi)
                ldmatrix_x4(af[mi], st + (uint32_t)((wm * 32 + mi * 16 + r_lm) * LDSB + kcol * 2));
#pragma unroll
            for (int nj = 0; nj < 4; ++nj) {
                uint32_t bf[4];
                ldmatrix_x4(bf, st + TILEB + (uint32_t)((wn * 64 + nj * 16 + r_lm) * LDSB + kcol * 2));
#pragma unroll
                for (int mi = 0; mi < 2; ++mi)
#pragma unroll
                    for (int q = 0; q < 2; ++q)
                        mma_f16(acc[mi][nj * 2 + q], af[mi], bf[q], bf[2 + q]);
            }
        }
    }

    int tg = lane >> 2, tq = lane & 3;
#pragma unroll
    for (int mi = 0; mi < 2; ++mi) {
        int r = wm * 32 + mi * 16 + tg;
#pragma unroll
        for (int ni = 0; ni < 8; ++ni) {
            int cix = wn * 64 + ni * 8 + tq * 2;
            *(float2*)(g_send2 + ((size_t)h * NROW + r) * 128 + cix) =
                make_float2(acc[mi][ni][0], acc[mi][ni][1]);
            *(float2*)(g_send2 + ((size_t)h * NROW + r + 8) * 128 + cix) =
                make_float2(acc[mi][ni][2], acc[mi][ni][3]);
        }
    }
}

// ---------------- combine ------------------------------------------------------------
__global__ __launch_bounds__(256) void combine_kernel() {
    int idx = blockIdx.x * blockDim.x + threadIdx.x;
    int n = idx & (NST - 1);
    int b = (idx >> 6) & (BSZ - 1);
    int h = idx >> 9;
    float wTre = g_wTre[h * NST + n];
    float wTim = g_wTim[h * NST + n];
    float cr = 0.0f, ci = 0.0f;
#pragma unroll
    for (int seg = 0; seg < SEG; ++seg) {
        size_t cb = ((size_t)h * NROW + b * SEG + seg) * 128;
        g_car[cb + n]      = __float2half_rn(cr);
        g_car[cb + 64 + n] = __float2half_rn(ci);
        if (seg < SEG - 1) {
            float sr = g_send2[cb + n];
            float si = g_send2[cb + 64 + n];
            float nr = fmaf(wTre, cr, fmaf(-wTim, ci, sr));
            float ni = fmaf(wTim, cr, fmaf(wTre, ci, si));
            cr = nr; ci = ni;
        }
    }
}

// ---------------- scan GEMM: yT = gelu([Uh|Ul|Uh|CAR] @ [Th|Th|Tl|E]^T) -------------
__global__ void __launch_bounds__(256, 2) scan_gemm() {
    extern __shared__ char smem[];
    uint32_t sbase = smem_u32(smem);
    int tid = threadIdx.x, wid = tid >> 5, lane = tid & 31;
    int h = blockIdx.x;
    int wm = wid >> 1, wn = wid & 1;

    float acc[2][8][4];
#pragma unroll
    for (int i = 0; i < 2; i++)
#pragma unroll
        for (int j = 0; j < 8; j++)
#pragma unroll
            for (int q = 0; q < 4; q++) acc[i][j][q] = 0.0f;

    int lr = tid >> 1;
    int lc = (tid & 1) * 16;
    const fp16* up = g_usplit + ((size_t)h * NROW + lr) * 256 + lc;
    const fp16* cp = g_car + ((size_t)h * NROW + lr) * 128 + lc;
    const fp16* wp = g_WY + ((size_t)h * SEGT + lr) * 512 + lc;
    uint32_t soff = (uint32_t)(lr * LDSB + lc * 2);

    const int nch = 16;
    auto issue = [&](int c, int s) {
        uint32_t st = sbase + (uint32_t)s * STAGEB;
        const fp16* ab; int ga;
        if (c < 8)       { ab = up; ga = c * 32; }
        else if (c < 12) { ab = up; ga = (c - 8) * 32; }
        else             { ab = cp; ga = (c - 12) * 32; }
        CP_ASYNC16(st + soff,      ab + ga);
        CP_ASYNC16(st + soff + 16, ab + ga + 8);
        int gw = c * 32;
        CP_ASYNC16(st + TILEB + soff,      wp + gw);
        CP_ASYNC16(st + TILEB + soff + 16, wp + gw + 8);
    };
    issue(0, 0); CP_COMMIT();
    issue(1, 1); CP_COMMIT();

    int r_lm = (lane & 7) + ((lane >> 3) & 1) * 8;
    int k_lm = ((lane >> 4) & 1) * 8;

    for (int c = 0; c < nch; ++c) {
        CP_WAIT(1);
        __syncthreads();
        if (c + 2 < nch) { issue(c + 2, (c + 2) % NSTAGE); CP_COMMIT(); }
        uint32_t st = sbase + (uint32_t)(c % NSTAGE) * STAGEB;
#pragma unroll
        for (int ks = 0; ks < 2; ++ks) {
            int kcol = ks * 16 + k_lm;
            uint32_t af[2][4];
#pragma unroll
            for (int mi = 0; mi < 2; ++mi)
                ldmatrix_x4(af[mi], st + (uint32_t)((wm * 32 + mi * 16 + r_lm) * LDSB + kcol * 2));
#pragma unroll
            for (int nj = 0; nj < 4; ++nj) {
                uint32_t bf[4];
                ldmatrix_x4(bf, st + TILEB + (uint32_t)((wn * 64 + nj * 16 + r_lm) * LDSB + kcol * 2));
#pragma unroll
                for (int mi = 0; mi < 2; ++mi)
#pragma unroll
                    for (int q = 0; q < 2; ++q)
                        mma_f16(acc[mi][nj * 2 + q], af[mi], bf[q], bf[2 + q]);
            }
        }
    }

    int tg = lane >> 2, tq = lane & 3;
#pragma unroll
    for (int mi = 0; mi < 2; ++mi) {
        int r = wm * 32 + mi * 16 + tg;
#pragma unroll
        for (int ni = 0; ni < 8; ++ni) {
            int cix = wn * 64 + ni * 8 + tq * 2;
            float v0 = gelu_f(acc[mi][ni][0]), v1 = gelu_f(acc[mi][ni][1]);
            float v2 = gelu_f(acc[mi][ni][2]), v3 = gelu_f(acc[mi][ni][3]);
            *(fp162*)(g_yT + ((size_t)h * NROW + r) * SEGT + cix) = __floats2half2_rn(v0, v1);
            *(fp162*)(g_yT + ((size_t)h * NROW + r + 8) * SEGT + cix) = __floats2half2_rn(v2, v3);
        }
    }
}

// ---------------- yT (H, B*L) -> yf (B*L, H) fp16 transpose --------------------------
__global__ __launch_bounds__(256) void yt_transpose_kernel() {
    __shared__ fp16 tile[32][34];
    int bl0 = blockIdx.x * 32, h0 = blockIdx.y * 32;
    int tx = threadIdx.x & 31, ty = threadIdx.x >> 5;
#pragma unroll
    for (int i = 0; i < 32; i += 8)
        tile[ty + i][tx] = g_yT[(size_t)(h0 + ty + i) * (BSZ * LSEQ) + bl0 + tx];
    __syncthreads();
#pragma unroll
    for (int i = 0; i < 32; i += 8)
        g_yf[(size_t)(bl0 + ty + i) * HDIM + h0 + tx] = tile[tx][ty + i];
}

// ---------------- weight convert -----------------------------------------------------
__global__ void convert_w_kernel(const float* __restrict__ wout,
                                 const float* __restrict__ w1,
                                 const float* __restrict__ w2) {
    int i = blockIdx.x * blockDim.x + threadIdx.x;
    const int n1 = 2 * HDIM * HDIM;
    const int n2 = HDIM * HDIM;
    if (i < n1) {
        g_woutf[i] = __float2half_rn(wout[i]);
    } else if (i < n1 + n2) {
        g_w1f[i - n1] = __float2half_rn(w1[i - n1]);
    } else {
        g_w2f[i - n1 - n2] = __float2half_rn(w2[i - n1 - n2]);
    }
}

// ============ main GEMM: C = A_f16 @ B_f16^T + bias (KC=32, proven config) =========
// mode 0: fp32 out ; 1: relu + fp16 out ; 2: fp16 out (no relu)
__global__ void __launch_bounds__(256, 2)
gemm_mma(const fp16* __restrict__ A, const fp16* __restrict__ B,
         const float* __restrict__ bias,
         float* __restrict__ C, fp16* __restrict__ Cf,
         int K, int N, int mode) {
    extern __shared__ char smem[];
    uint32_t sbase = smem_u32(smem);
    int tid = threadIdx.x, wid = tid >> 5, lane = tid & 31;
    int row0 = blockIdx.y * 128, col0 = blockIdx.x * 128;
    int wm = wid >> 1, wn = wid & 1;

    float acc[2][8][4];
#pragma unroll
    for (int i = 0; i < 2; i++)
#pragma unroll
        for (int j = 0; j < 8; j++)
#pragma unroll
            for (int q = 0; q < 4; q++) acc[i][j][q] = 0.0f;

    int lr = tid >> 1;
    int lc = (tid & 1) * 16;
    const fp16* ap = A + (size_t)(row0 + lr) * K + lc;
    const fp16* bp = B + (size_t)(col0 + lr) * K + lc;
    uint32_t soff = (uint32_t)(lr * LDSB + lc * 2);

    int nch = K / 32;

    auto issue = [&](int c, int s) {
        uint32_t st = sbase + (uint32_t)s * STAGEB;
        int go = c * 32;
        CP_ASYNC16(st + soff,      ap + go);
        CP_ASYNC16(st + soff + 16, ap + go + 8);
        CP_ASYNC16(st + TILEB + soff,      bp + go);
        CP_ASYNC16(st + TILEB + soff + 16, bp + go + 8);
    };

    issue(0, 0); CP_COMMIT();
    if (nch > 1) { issue(1, 1); CP_COMMIT(); }

    int r_lm = (lane & 7) + ((lane >> 3) & 1) * 8;
    int k_lm = ((lane >> 4) & 1) * 8;

    for (int c = 0; c < nch; ++c) {
        CP_WAIT(1);
        __syncthreads();
        if (c + 2 < nch) { issue(c + 2, (c + 2) % NSTAGE); CP_COMMIT(); }

        uint32_t st = sbase + (uint32_t)(c % NSTAGE) * STAGEB;
#pragma unroll
        for (int ks = 0; ks < 2; ++ks) {
            int kcol = ks * 16 + k_lm;
            uint32_t af[2][4];
#pragma unroll
            for (int mi = 0; mi < 2; ++mi)
                ldmatrix_x4(af[mi], st + (uint32_t)((wm * 32 + mi * 16 + r_lm) * LDSB + kcol * 2));
#pragma unroll
            for (int nj = 0; nj < 4; ++nj) {
                uint32_t bf[4];
                ldmatrix_x4(bf, st + TILEB + (uint32_t)((wn * 64 + nj * 16 + r_lm) * LDSB + kcol * 2));
#pragma unroll
                for (int mi = 0; mi < 2; ++mi)
#pragma unroll
                    for (int q = 0; q < 2; ++q)
                        mma_f16(acc[mi][nj * 2 + q], af[mi], bf[q], bf[2 + q]);
            }
        }
    }

    int tg = lane >> 2, tq = lane & 3;
#pragma unroll
    for (int mi = 0; mi < 2; ++mi) {
        int r = row0 + wm * 32 + mi * 16 + tg;
#pragma unroll
        for (int ni = 0; ni < 8; ++ni) {
            int cix = col0 + wn * 64 + ni * 8 + tq * 2;
            float b0 = bias[cix], b1 = bias[cix + 1];
            float v0 = acc[mi][ni][0] + b0, v1 = acc[mi][ni][1] + b1;
            float v2 = acc[mi][ni][2] + b0, v3 = acc[mi][ni][3] + b1;
            if (mode == 0) {
                *(float2*)(C + (size_t)r * N + cix) = make_float2(v0, v1);
                *(float2*)(C + (size_t)(r + 8) * N + cix) = make_float2(v2, v3);
            } else {
                if (mode == 1) {
                    v0 = fmaxf(v0, 0.0f); v1 = fmaxf(v1, 0.0f);
                    v2 = fmaxf(v2, 0.0f); v3 = fmaxf(v3, 0.0f);
                }
                *(fp162*)(Cf + (size_t)r * N + cix) = __floats2half2_rn(v0, v1);
                *(fp162*)(Cf + (size_t)(r + 8) * N + cix) = __floats2half2_rn(v2, v3);
            }
        }
    }
}

// ---------------- block reduce helper ---------------------------------------------
__device__ __forceinline__ float2 block_reduce_2(float a, float b) {
    unsigned m = 0xffffffffu;
#pragma unroll
    for (int o = 16; o > 0; o >>= 1) {
        a += __shfl_down_sync(m, a, o);
        b += __shfl_down_sync(m, b, o);
    }
    __shared__ float sa[4], sb[4];
    int w = threadIdx.x >> 5, lane = threadIdx.x & 31;
    if (lane == 0) { sa[w] = a; sb[w] = b; }
    __syncthreads();
    if (threadIdx.x == 0) {
        float ta = sa[0] + sa[1] + sa[2] + sa[3];
        float tb = sb[0] + sb[1] + sb[2] + sb[3];
        sa[0] = ta; sb[0] = tb;
    }
    __syncthreads();
    return make_float2(sa[0], sb[0]);
}

// ---------------- GLU + residual + LN1 (fp16 z in) ---------------------------------
__global__ __launch_bounds__(128) void glu_ln_kernel(const fp16* __restrict__ z,
                                                     const float* __restrict__ x,
                                                     const float* __restrict__ g1,
                                                     const float* __restrict__ b1,
                                                     float* __restrict__ xln,
                                                     fp16* __restrict__ xf) {
    int row = blockIdx.x, tid = threadIdx.x;
    const fp162* zr = (const fp162*)(z + (size_t)row * (2 * HDIM));
    const float4* xr = (const float4*)(x + (size_t)row * HDIM);
    fp162 a01 = zr[tid * 2], a23 = zr[tid * 2 + 1];
    fp162 g01 = zr[256 + tid * 2], g23 = zr[256 + tid * 2 + 1];
    float4 xv = xr[tid];
    float2 a0 = __half22float2(a01), a2 = __half22float2(a23);
    float2 gg0 = __half22float2(g01), gg2 = __half22float2(g23);
    float4 v;
    v.x = xv.x + a0.x / (1.0f + __expf(-gg0.x));
    v.y = xv.y + a0.y / (1.0f + __expf(-gg0.y));
    v.z = xv.z + a2.x / (1.0f + __expf(-gg2.x));
    v.w = xv.w + a2.y / (1.0f + __expf(-gg2.y));
    float s  = v.x + v.y + v.z + v.w;
    float s2 = v.x*v.x + v.y*v.y + v.z*v.z + v.w*v.w;
    float2 tot = block_reduce_2(s, s2);
    float mu = tot.x * (1.0f / HDIM);
    float var = tot.y * (1.0f / HDIM) - mu * mu;
    float rstd = rsqrtf(var + 1e-5f);
    float4 gv = ((const float4*)g1)[tid];
    float4 bv = ((const float4*)b1)[tid];
    float4 o;
    o.x = (v.x - mu) * rstd * gv.x + bv.x;
    o.y = (v.y - mu) * rstd * gv.y + bv.y;
    o.z = (v.z - mu) * rstd * gv.z + bv.z;
    o.w = (v.w - mu) * rstd * gv.w + bv.w;
    ((float4*)(xln + (size_t)row * HDIM))[tid] = o;
    fp162* xf2 = (fp162*)(xf + (size_t)row * HDIM);
    xf2[tid*2]   = __floats2half2_rn(o.x, o.y);
    xf2[tid*2+1] = __floats2half2_rn(o.z, o.w);
}

// ---------------- residual + LN2 ----------------------------------------------------
__global__ __launch_bounds__(128) void final_ln_kernel(const float* __restrict__ xln,
                                                       const float* __restrict__ y2,
                                                       const float* __restrict__ g2,
                                                       const float* __restrict__ b2,
                                                       float* __restrict__ out) {
    int row = blockIdx.x, tid = threadIdx.x;
    float4 a = ((const float4*)(xln + (size_t)row * HDIM))[tid];
    float4 b = ((const float4*)(y2  + (size_t)row * HDIM))[tid];
    float4 v;
    v.x = a.x + b.x; v.y = a.y + b.y; v.z = a.z + b.z; v.w = a.w + b.w;
    float s  = v.x + v.y + v.z + v.w;
    float s2 = v.x*v.x + v.y*v.y + v.z*v.z + v.w*v.w;
    float2 tot = block_reduce_2(s, s2);
    float mu = tot.x * (1.0f / HDIM);
    float var = tot.y * (1.0f / HDIM) - mu * mu;
    float rstd = rsqrtf(var + 1e-5f);
    float4 gv = ((const float4*)g2)[tid];
    float4 bv = ((const float4*)b2)[tid];
    float4 o;
    o.x = (v.x - mu) * rstd * gv.x + bv.x;
    o.y = (v.y - mu) * rstd * gv.y + bv.y;
    o.z = (v.z - mu) * rstd * gv.z + bv.z;
    o.w = (v.w - mu) * rstd * gv.w + bv.w;
    ((float4*)(out + (size_t)row * HDIM))[tid] = o;
}

// ---------------- launch ------------------------------------------------------------
extern "C" void kernel_launch(void* const* d_in, const int* in_sizes, int n_in,
                              void* d_out, int out_size) {
    const float* x      = (const float*)d_in[0];
    const float* log_dt = (const float*)d_in[1];
    const float* A_re   = (const float*)d_in[2];
    const float* A_im   = (const float*)d_in[3];
    const float* C_re   = (const float*)d_in[4];
    const float* C_im   = (const float*)d_in[5];
    const float* D_skip = (const float*)d_in[6];
    const float* W_out  = (const float*)d_in[7];
    const float* b_out  = (const float*)d_in[8];
    const float* g1     = (const float*)d_in[9];
    const float* beta1  = (const float*)d_in[10];
    const float* g2     = (const float*)d_in[11];
    const float* beta2  = (const float*)d_in[12];
    const float* W1     = (const float*)d_in[13];
    const float* bc1    = (const float*)d_in[14];
    const float* W2     = (const float*)d_in[15];
    const float* bc2    = (const float*)d_in[16];
    float* out = (float*)d_out;

    fp16 *yf, *zf, *xf, *y1f, *woutf, *w1f, *w2f;
    float *xln, *y2;
    cudaGetSymbolAddress((void**)&yf,  g_yf);
    cudaGetSymbolAddress((void**)&zf,  g_zf);
    cudaGetSymbolAddress((void**)&xln, g_xln);
    cudaGetSymbolAddress((void**)&xf,  g_xf);
    cudaGetSymbolAddress((void**)&y1f, g_y1f);
    cudaGetSymbolAddress((void**)&y2,  g_y2);
    cudaGetSymbolAddress((void**)&woutf, g_woutf);
    cudaGetSymbolAddress((void**)&w1f, g_w1f);
    cudaGetSymbolAddress((void**)&w2f, g_w2f);

    cudaFuncSetAttribute(gemm_mma,  cudaFuncAttributeMaxDynamicSharedMemorySize, GEMM_SMEM);
    cudaFuncSetAttribute(send_gemm, cudaFuncAttributeMaxDynamicSharedMemorySize, GEMM_SMEM);
    cudaFuncSetAttribute(scan_gemm, cudaFuncAttributeMaxDynamicSharedMemorySize, GEMM_SMEM);

    // 1) discretize + operator builds (coalesced)
    precompute_kernel<<<HDIM, NST>>>(log_dt, A_re, A_im, C_re, C_im);
    transpose_split_kernel<<<dim3(LSEQ / 32, HDIM / 32, BSZ), 256>>>(x);
    build_kk_e_kernel<<<HDIM, 128>>>();
    build_t_kernel<<<HDIM, 256>>>(D_skip);
    build_wf_kernel<<<HDIM, 256>>>();
    convert_w_kernel<<<(4 * HDIM * HDIM + 255) / 256, 256>>>(W_out, W1, W2);

    // 2) scan as GEMMs
    send_gemm<<<HDIM, 256, GEMM_SMEM>>>();
    combine_kernel<<<(HDIM * BSZ * NST) / 256, 256>>>();
    scan_gemm<<<HDIM, 256, GEMM_SMEM>>>();
    yt_transpose_kernel<<<dim3((BSZ * LSEQ) / 32, HDIM / 32), 256>>>();

    // 3) GLU projection (fp16 z out) + rest of layer
    gemm_mma<<<dim3((2 * HDIM) / 128, ROWS / 128), 256, GEMM_SMEM>>>(
        yf, woutf, b_out, nullptr, zf, HDIM, 2 * HDIM, 2);

    glu_ln_kernel<<<ROWS, 128>>>(zf, x, g1, beta1, xln, xf);

    gemm_mma<<<dim3(HDIM / 128, ROWS / 128), 256, GEMM_SMEM>>>(
        xf, w1f, bc1, nullptr, y1f, HDIM, HDIM, 1);

    gemm_mma<<<dim3(HDIM / 128, ROWS / 128), 256, GEMM_SMEM>>>(
        y1f, w2f, bc2, y2, nullptr, HDIM, HDIM, 0);

    final_ln_kernel<<<ROWS, 128>>>(xln, y2, g2, beta2, out);
}